// round 16
// baseline (speedup 1.0000x reference)
#include <cuda_runtime.h>
#include <cuda_fp16.h>
#include <cstdint>

// Problem constants
#define B_   4
#define C_   256
#define H_   160
#define W_   160
#define HW_  (H_ * W_)          // 25600
#define N_   512
#define PH_  8
#define PW_  64

#define GRID_R   1184           // 148 SMs x 8 resident blocks (persistent)
#define NBASES   8192           // (n, py, h) work bases
#define MAXB     7              // max bases per block

// 50 MB scratch: features transposed to (B, H*W, C) in fp16 so channel reads
// coalesce AND the whole table stays resident in the 126 MB L2.
__device__ __half g_featT[(size_t)B_ * HW_ * C_];

// ---------------------------------------------------------------------------
// Kernel 1: (B, C, H*W) fp32 -> (B, H*W, C) fp16 tiled transpose.
// ---------------------------------------------------------------------------
__global__ void __launch_bounds__(256) transpose_kernel(const float* __restrict__ in)
{
    __shared__ float tile[64][33];

    const int b     = blockIdx.z;
    const int cBase = blockIdx.y * 64;
    const int sBase = blockIdx.x * 32;
    const int tx = threadIdx.x;
    const int ty = threadIdx.y;

    const float* src = in + (size_t)b * C_ * HW_;
#pragma unroll
    for (int j = 0; j < 64; j += 8)
        tile[ty + j][tx] = __ldcs(&src[(size_t)(cBase + ty + j) * HW_ + sBase + tx]);

    __syncthreads();

    __half2* dst2 = (__half2*)(g_featT + (size_t)b * HW_ * C_);
#pragma unroll
    for (int m = 0; m < 4; ++m) {
        const int s = ty + 8 * m;
        const float lo = tile[2 * tx][s];
        const float hi = tile[2 * tx + 1][s];
        dst2[((size_t)(sBase + s) * C_ + cBase) / 2 + tx] = __floats2half2_rn(lo, hi);
    }
}

// ---------------------------------------------------------------------------
// Kernel 2: persistent-block rotated ROI align with cross-item pipelining.
// 1184 blocks x 128 threads, all co-resident (8/SM). Block owns <=7 bases
// (n, py, h); each base = two sub-items (channel halves, 8 KB tile each).
// Steady state: gathers for sub-item s+1 issue first in each window, then
// phase-2 stores of sub-item s run in their latency shadow.
// ---------------------------------------------------------------------------
__global__ void __launch_bounds__(128, 8) rroi_kernel(const float* __restrict__ rois,
                                                      float* __restrict__ out)
{
    __shared__ uint4 tiles[2][32 * 16];     // double-buffered 8 KB half-tiles
    __shared__ uint4 s_wh[MAXB][32];        // half2-broadcast weights per base/px
    __shared__ int4  s_off4[MAXB][32];      // corner offsets (uint4 units)

    const int bid = blockIdx.x;
    const int t   = threadIdx.x;
    const int nb  = (NBASES - bid + GRID_R - 1) / GRID_R;   // 6 or 7
    const int ns  = nb * 2;                 // sub-items (channel halves)

    // ---- precompute ALL bases up front (one barrier) ----
    for (int j = t >> 5; j < nb; j += 4) {
        const int base = bid + j * GRID_R;
        const int n  = base >> 4;
        const int py = (base >> 1) & 7;
        const int h  = base & 1;
        const int pxl = t & 31;
        const int px  = h * 32 + pxl;

        const float* r = rois + n * 6;
        const int   b  = (int)r[0];
        const float cx = r[1];
        const float cy = r[2];
        const float rh = r[3];
        const float rw = r[4];
        const float th = r[5];

        const float sx = rw * (1.0f / PW_);
        const float sy = rh * (1.0f / PH_);
        const float ct = cosf(th);
        const float st = sinf(th);

        const float yy = ((float)py + 0.5f - PH_ * 0.5f) * sy;
        const float xx = ((float)px + 0.5f - PW_ * 0.5f) * sx;

        const float x = ct * xx + st * yy + cx;
        const float y = -st * xx + ct * yy + cy;

        const float x0f = floorf(x);
        const float y0f = floorf(y);
        const float lx = x - x0f;
        const float ly = y - y0f;
        const int x0 = (int)x0f;
        const int y0 = (int)y0f;
        const int x1 = x0 + 1;
        const int y1 = y0 + 1;

        const bool vx0 = (x0 >= 0) && (x0 < W_);
        const bool vx1 = (x1 >= 0) && (x1 < W_);
        const bool vy0 = (y0 >= 0) && (y0 < H_);
        const bool vy1 = (y1 >= 0) && (y1 < H_);

        const float w00 = (1.0f - lx) * (1.0f - ly) * ((vy0 && vx0) ? 1.0f : 0.0f);
        const float w01 = lx          * (1.0f - ly) * ((vy0 && vx1) ? 1.0f : 0.0f);
        const float w10 = (1.0f - lx) * ly          * ((vy1 && vx0) ? 1.0f : 0.0f);
        const float w11 = lx          * ly          * ((vy1 && vx1) ? 1.0f : 0.0f);

        uint4 wh;
        ((__half2*)&wh)[0] = __half2half2(__float2half_rn(w00));
        ((__half2*)&wh)[1] = __half2half2(__float2half_rn(w01));
        ((__half2*)&wh)[2] = __half2half2(__float2half_rn(w10));
        ((__half2*)&wh)[3] = __half2half2(__float2half_rn(w11));

        const int x0c = min(max(x0, 0), W_ - 1);
        const int x1c = min(max(x1, 0), W_ - 1);
        const int y0c = min(max(y0, 0), H_ - 1);
        const int y1c = min(max(y1, 0), H_ - 1);

        const int gbase = b * HW_;
        int4 ov;   // offsets in uint4 units (8 halfs): pos * C_/8 = pos * 32
        ov.x = (gbase + y0c * W_ + x0c) * (C_ / 8);
        ov.y = (gbase + y0c * W_ + x1c) * (C_ / 8);
        ov.z = (gbase + y1c * W_ + x0c) * (C_ / 8);
        ov.w = (gbase + y1c * W_ + x1c) * (C_ / 8);

        s_wh[j][pxl]   = wh;
        s_off4[j][pxl] = ov;
    }
    __syncthreads();

    const int warp = t >> 5;
    const int lane = t & 31;
    const int sel  = lane >> 4;             // which px of the pair
    const int g    = lane & 15;             // channel group within half
    const int q_   = t & 7;                 // phase-2 px quad
    const int gg   = t >> 4;                // unused placeholder (kept simple below)
    const uint4* featU = (const uint4*)g_featT;

    // half2 interpolation
    auto interp = [&](const uint4& wv, const uint4& c0, const uint4& c1,
                      const uint4& c2, const uint4& c3) -> uint4 {
        const __half2 w0 = ((const __half2*)&wv)[0];
        const __half2 w1 = ((const __half2*)&wv)[1];
        const __half2 w2 = ((const __half2*)&wv)[2];
        const __half2 w3 = ((const __half2*)&wv)[3];
        uint4 packed;
#pragma unroll
        for (int q = 0; q < 4; ++q) {
            __half2 acc = __hmul2(w0, ((const __half2*)&c0)[q]);
            acc = __hfma2(w1, ((const __half2*)&c1)[q], acc);
            acc = __hfma2(w2, ((const __half2*)&c2)[q], acc);
            acc = __hfma2(w3, ((const __half2*)&c3)[q], acc);
            ((__half2*)&packed)[q] = acc;
        }
        return packed;
    };

    // ---- prologue: phase 1 of sub-item 0 (base 0, channel half 0) ----
#pragma unroll
    for (int i = 0; i < 4; ++i) {
        const int p   = warp * 4 + i;
        const int pxl = 2 * p + sel;
        const int rot = p >> 1;
        const int4 o  = s_off4[0][pxl];
        const uint4 c0 = __ldg(featU + o.x + g);
        const uint4 c1 = __ldg(featU + o.y + g);
        const uint4 c2 = __ldg(featU + o.z + g);
        const uint4 c3 = __ldg(featU + o.w + g);
        tiles[0][pxl * 16 + ((g + rot) & 15)] = interp(s_wh[0][pxl], c0, c1, c2, c3);
    }

    // ---- steady-state loop: one barrier per sub-item ----
    const int gg2  = t >> 3;                // phase-2 channel group (0..15)
    const int col2 = (gg2 + q_) & 15;       // conflict-free LDS column

    for (int s = 0; s < ns; ++s) {
        __syncthreads();

        const uint4* src = tiles[s & 1];
        uint4*       dst = tiles[(s + 1) & 1];
        const bool  more = (s + 1) < ns;

        // current sub-item (being stored)
        const int js  = s >> 1;
        const int chs = s & 1;
        const int bs  = bid + js * GRID_R;
        const int n_s = bs >> 4;
        const int py_s = (bs >> 1) & 7;
        const int h_s  = bs & 1;
        const unsigned ob = (unsigned)n_s * (C_ * PH_ * PW_) + (unsigned)py_s * PW_;
        const unsigned pxg = (unsigned)h_s * 32 + 4 * q_;

        // next sub-item (being gathered)
        const int jn  = (s + 1) >> 1;
        const int chn = (s + 1) & 1;

        uint4 v0, v1, v2, v3;

#pragma unroll
        for (int i = 0; i < 4; ++i) {
            // A: issue gathers for next sub-item (fill the shadow)
            uint4 c0, c1, c2, c3;
            int pxl = 0, rot = 0;
            if (more) {
                const int p = warp * 4 + i;
                pxl = 2 * p + sel;
                rot = p >> 1;
                const int4 o  = s_off4[jn][pxl];
                const int cb  = chn * 16 + g;
                c0 = __ldg(featU + o.x + cb);
                c1 = __ldg(featU + o.y + cb);
                c2 = __ldg(featU + o.z + cb);
                c3 = __ldg(featU + o.w + cb);
            }

            // B: phase 2 of current sub-item (runs while gathers are in flight)
            if (i == 0) {
                v0 = src[(4 * q_ + 0) * 16 + col2];
                v1 = src[(4 * q_ + 1) * 16 + col2];
                v2 = src[(4 * q_ + 2) * 16 + col2];
                v3 = src[(4 * q_ + 3) * 16 + col2];
            }
            {
                const int qq = i;
                const float2 f0 = __half22float2(((const __half2*)&v0)[qq]);
                const float2 f1 = __half22float2(((const __half2*)&v1)[qq]);
                const float2 f2 = __half22float2(((const __half2*)&v2)[qq]);
                const float2 f3 = __half22float2(((const __half2*)&v3)[qq]);
                const float4 sA = make_float4(f0.x, f1.x, f2.x, f3.x);
                const float4 sB = make_float4(f0.y, f1.y, f2.y, f3.y);
                const unsigned c = (unsigned)((chs * 16 + gg2) * 8 + 2 * qq);
                __stcs((float4*)(out + ob + c       * (PH_ * PW_) + pxg), sA);
                __stcs((float4*)(out + ob + (c + 1) * (PH_ * PW_) + pxg), sB);
            }

            // C: consume gathers -> interp -> STS
            if (more) {
                dst[pxl * 16 + ((g + rot) & 15)] =
                    interp(s_wh[jn][pxl], c0, c1, c2, c3);
            }
        }
    }
    (void)gg;
}

// ---------------------------------------------------------------------------
extern "C" void kernel_launch(void* const* d_in, const int* in_sizes, int n_in,
                              void* d_out, int out_size)
{
    const float* features = (const float*)d_in[0];
    const float* rois     = (const float*)d_in[1];
    float* out            = (float*)d_out;

    dim3 tgrid(HW_ / 32, C_ / 64, B_);
    dim3 tblk(32, 8);
    transpose_kernel<<<tgrid, tblk>>>(features);

    rroi_kernel<<<GRID_R, 128>>>(rois, out);
}